// round 2
// baseline (speedup 1.0000x reference)
#include <cuda_runtime.h>
#include <cstdint>

#define TPB 256
#define MAXC 9605
#define CAP 1024
#define MAXU 1024

// ---- device-global scratch (no allocations allowed) ----
__device__ int   g_union_n;
__device__ int   g_ucols[MAXU];
__device__ int   g_ulab[MAXU];
__device__ float g_rank[8192];

// ---- monotone float <-> orderable uint mapping ----
__device__ __forceinline__ unsigned ordf(float f) {
    unsigned u = __float_as_uint(f);
    return (u & 0x80000000u) ? ~u : (u | 0x80000000u);
}
__device__ __forceinline__ float unordf(unsigned k) {
    unsigned u = (k & 0x80000000u) ? (k & 0x7fffffffu) : ~k;
    return __uint_as_float(u);
}
__device__ __forceinline__ float sigf(float v) { return 1.0f / (1.0f + expf(-v)); }

// ---- K_prep: one block. reset -> wl dtype detect -> union list build. ----
// Detect: scan LC/4 words (== full array if 1-byte bool; first quarter if
// 4-byte). int32{0,1}/float32{0,1.0f} words are in {0,1,0x3F800000}; a bool
// layout puts some true byte at offset%4!=0 with prob 1-(1/4)^(~400) -> any
// other word pattern means 1-byte elements.
__global__ void k_prep(const void* __restrict__ wl, int C, int L) {
    __shared__ int s_weird;
    const int tid = threadIdx.x, nt = blockDim.x;
    if (tid == 0) { g_union_n = 0; s_weird = 0; }
    __syncthreads();
    const int nwords = (L * C) / 4;
    const unsigned* w = (const unsigned*)wl;
    int weird = 0;
    for (int i = tid; i < nwords; i += nt) {
        unsigned v = w[i];
        if (v != 0u && v != 1u && v != 0x3F800000u) weird = 1;
    }
    if (weird) atomicOr(&s_weird, 1);
    __syncthreads();
    const int e1 = s_weird;  // 1 => 1-byte elements
    for (int c = tid; c < C; c += nt) {
        for (int l = 0; l < L; ++l) {
            bool t;
            if (e1) t = ((const unsigned char*)wl)[(size_t)l * C + c] != 0;
            else    t = ((const unsigned*)wl)[(size_t)l * C + c] != 0u;
            if (t) {
                int p = atomicAdd(&g_union_n, 1);
                if (p < MAXU) { g_ucols[p] = c; g_ulab[p] = l; }
            }
        }
    }
}

// ---- K_main: one block per sample row. ----
__global__ __launch_bounds__(TPB) void k_main(const float* __restrict__ x,
                                              const float* __restrict__ y,
                                              int C, int L) {
    __shared__ float srow[MAXC];
    __shared__ __align__(8) float cand[CAP];
    __shared__ float tmaxs[TPB];
    __shared__ float sfirst[8];
    __shared__ unsigned s_gt, s_umax, s_lab[8];
    __shared__ int   s_candn;
    __shared__ float s_m, s_x16;

    const int tid = threadIdx.x;
    const int b   = blockIdx.x;
    const float* xr = x + (size_t)b * C;
    const float* yr = y + (size_t)b * C;

    if (tid == 0) { s_gt = 0u; s_candn = 0; s_umax = 0u; }
    if (tid < 8)  s_lab[tid] = 0u;   // ordkey 0 is below every real float
    __syncthreads();

    int un = g_union_n; if (un > MAXU) un = MAXU;

    // --- gather y at union columns -> gt-label bits ---
    for (int i = tid; i < un; i += TPB) {
        int c = g_ucols[i];
        if (__ldg(yr + c) > 0.0f) atomicOr(&s_gt, 1u << g_ulab[i]);
    }

    // --- stream x row into SMEM via LDG.128 (peel to 16B alignment) ---
    float tmax = -INFINITY;
    {
        int off  = (int)(((uintptr_t)xr & 15u) >> 2);   // misaligned elems
        int peel = (4 - off) & 3; if (peel > C) peel = C;
        for (int c = tid; c < peel; c += TPB) {
            float v = __ldg(xr + c); srow[c] = v; tmax = fmaxf(tmax, v);
        }
        const int nv = (C - peel) >> 2;
        const float4* xv = (const float4*)(xr + peel);
        #pragma unroll 4
        for (int i = tid; i < nv; i += TPB) {
            float4 v = __ldg(xv + i);
            int c = peel + (i << 2);
            srow[c]   = v.x; srow[c+1] = v.y;
            srow[c+2] = v.z; srow[c+3] = v.w;
            tmax = fmaxf(tmax, fmaxf(fmaxf(v.x, v.y), fmaxf(v.z, v.w)));
        }
        for (int c = peel + (nv << 2) + tid; c < C; c += TPB) {
            float v = __ldg(xr + c); srow[c] = v; tmax = fmaxf(tmax, v);
        }
    }
    tmaxs[tid] = tmax;
    __syncthreads();

    // snapshot x[b, 0..7] (non_gt quirk; fallback path may clobber srow)
    if (tid < 8) sfirst[tid] = (tid < C) ? srow[tid] : -INFINITY;

    // --- union max + per-label max over whitelist columns ---
    for (int i = tid; i < un; i += TPB) {
        unsigned k = ordf(srow[g_ucols[i]]);
        atomicMax(&s_umax, k);
        atomicMax(&s_lab[g_ulab[i]], k);
    }

    // --- m = 16th largest of 256 thread maxima (lower bound on global 16th) ---
    if (tid < 32) {
        float mval = -INFINITY;
        for (int r = 0; r < 16; ++r) {
            unsigned long long lb = 0ull;
            #pragma unroll
            for (int j = 0; j < 8; ++j) {
                int s = tid + 32 * j;
                unsigned long long k =
                    ((unsigned long long)ordf(tmaxs[s]) << 32) | (unsigned)s;
                if (k > lb) lb = k;
            }
            #pragma unroll
            for (int off = 16; off; off >>= 1) {
                unsigned long long o = __shfl_xor_sync(0xffffffffu, lb, off);
                if (o > lb) lb = o;
            }
            if (tid == 0) tmaxs[(int)(lb & 0xffffffffull)] = -INFINITY;
            mval = unordf((unsigned)(lb >> 32));
            __syncwarp();
        }
        if (tid == 0) s_m = mval;
    }
    __syncthreads();

    // --- gather ALL values >= m (count >= 16 guaranteed by construction) ---
    float m = s_m;
    for (int c = tid; c < C; c += TPB) {
        float v = srow[c];
        if (v >= m) {
            int p = atomicAdd(&s_candn, 1);
            if (p < CAP) cand[p] = v;
        }
    }
    __syncthreads();

    int nc = s_candn;
    if (nc <= CAP) {
        // fast path: 16 warp argmax-with-removal rounds over candidates
        if (tid < 32) {
            float xv = -INFINITY;
            for (int r = 0; r < 16; ++r) {
                unsigned long long lb = 0ull;
                for (int i = tid; i < nc; i += 32) {
                    unsigned long long k =
                        ((unsigned long long)ordf(cand[i]) << 32) | (unsigned)i;
                    if (k > lb) lb = k;
                }
                #pragma unroll
                for (int off = 16; off; off >>= 1) {
                    unsigned long long o = __shfl_xor_sync(0xffffffffu, lb, off);
                    if (o > lb) lb = o;
                }
                if (tid == 0) cand[(int)(lb & 0xffffffffull)] = -INFINITY;
                xv = unordf((unsigned)(lb >> 32));
                __syncwarp();
            }
            if (tid == 0) s_x16 = xv;
        }
    } else {
        // rare fallback: 16 block-wide argmax-with-removal rounds, full row
        unsigned long long* bk = (unsigned long long*)cand;  // reuse buffer
        for (int r = 0; r < 16; ++r) {
            unsigned long long lb = 0ull;
            for (int c = tid; c < C; c += TPB) {
                unsigned long long k =
                    ((unsigned long long)ordf(srow[c]) << 32) | (unsigned)c;
                if (k > lb) lb = k;
            }
            bk[tid] = lb;
            __syncthreads();
            if (tid < 32) {
                #pragma unroll
                for (int j = 1; j < 8; ++j) {
                    unsigned long long o = bk[tid + 32 * j];
                    if (o > lb) lb = o;
                }
                #pragma unroll
                for (int off = 16; off; off >>= 1) {
                    unsigned long long o = __shfl_xor_sync(0xffffffffu, lb, off);
                    if (o > lb) lb = o;
                }
                if (tid == 0) {
                    srow[(int)(lb & 0xffffffffull)] = -INFINITY;
                    if (r == 15) s_x16 = unordf((unsigned)(lb >> 32));
                }
            }
            __syncthreads();
        }
    }
    __syncthreads();

    // --- final scalar math for this row ---
    if (tid == 0) {
        unsigned gt = s_gt;
        float x16   = s_x16;
        float thres = sigf(fmaxf(x16, 0.0f));   // == max(sig(x16), 0.5)
        float x1, x2;
        if (gt) {
            int fg = __ffs(gt) - 1;             // first gt label
            x1 = sigf(unordf(s_lab[fg]));
            float ngr = -INFINITY;
            bool anyng = false;
            int Lc = (L < 8) ? L : 8;
            for (int l = 0; l < Lc; ++l) {
                if (!((gt >> l) & 1u)) { ngr = fmaxf(ngr, sfirst[l]); anyng = true; }
            }
            float nongt = anyng ? sigf(ngr) : 0.0f;  // ref quirk: xs[:, :L], init 0
            x2 = fmaxf(nongt, thres);
        } else {
            x1 = thres;
            x2 = sigf(unordf(s_umax));
        }
        float d = x2 - x1 + 0.1f;
        float s = 1.0f / (1.0f + expf(-10.0f * d));
        g_rank[b] = (d > 0.0f) ? 5.0f * s : s;
    }
}

// ---- K_reduce: deterministic fixed-order reduction of per-row ranks ----
__global__ void k_reduce(float* __restrict__ out, int B) {
    __shared__ float ss[256];
    float s = 0.0f;
    for (int i = threadIdx.x; i < B; i += 256) s += g_rank[i];
    ss[threadIdx.x] = s;
    __syncthreads();
    for (int h = 128; h; h >>= 1) {
        if (threadIdx.x < h) ss[threadIdx.x] += ss[threadIdx.x + h];
        __syncthreads();
    }
    if (threadIdx.x == 0) out[0] = ss[0];
}

extern "C" void kernel_launch(void* const* d_in, const int* in_sizes, int n_in,
                              void* d_out, int out_size) {
    const float* x  = (const float*)d_in[0];
    const float* y  = (const float*)d_in[1];
    // d_in[2] = y_neg: dead code in the reference, never read.
    const void*  wl = d_in[3];

    const int L  = 8;
    const int LC = in_sizes[3];      // L * C elements
    const int C  = LC / L;           // 9605
    const int B  = in_sizes[0] / C;  // 4096

    k_prep<<<1, 1024>>>(wl, C, L);
    k_main<<<B, TPB>>>(x, y, C, L);
    k_reduce<<<1, 256>>>((float*)d_out, B);
}

// round 4
// speedup vs baseline: 1.3828x; 1.3828x over previous
#include <cuda_runtime.h>
#include <cstdint>

#define TPB 256
#define CAP 1024
#define MAXU 1024

// ---- device-global scratch (no allocations allowed) ----
__device__ int   g_union_n;
__device__ int   g_weird;
__device__ int   g_ucols[MAXU];
__device__ int   g_ulab[MAXU];
__device__ float g_rank[8192];

// ---- monotone float <-> orderable uint mapping ----
__device__ __forceinline__ unsigned ordf(float f) {
    unsigned u = __float_as_uint(f);
    return (u & 0x80000000u) ? ~u : (u | 0x80000000u);
}
__device__ __forceinline__ float unordf(unsigned k) {
    unsigned u = (k & 0x80000000u) ? (k & 0x7fffffffu) : ~k;
    return __uint_as_float(u);
}
__device__ __forceinline__ float sigf(float v) { return 1.0f / (1.0f + expf(-v)); }

// ---- K_reset ----
__global__ void k_reset() { g_union_n = 0; g_weird = 0; }

// ---- K_detect: wl dtype sniff (full grid; the single-block version cost 22us).
// Words of int32{0,1}/float32{0,1.0f} are in {0,1,0x3F800000}; a 1-byte bool
// layout puts some true byte at offset%4 != 0 -> any other word pattern.
__global__ void k_detect(const unsigned* __restrict__ w, int n) {
    int i = blockIdx.x * blockDim.x + threadIdx.x;
    if (i < n) {
        unsigned v = w[i];
        if (v != 0u && v != 1u && v != 0x3F800000u) atomicOr(&g_weird, 1);
    }
}

// ---- K_build: compact (col,label) union list; label sets are disjoint. ----
__global__ void k_build(const void* __restrict__ wl, int C, int L) {
    int c = blockIdx.x * blockDim.x + threadIdx.x;
    if (c >= C) return;
    const int e1 = g_weird;  // 1 => 1-byte elements
    for (int l = 0; l < L; ++l) {
        bool t;
        if (e1) t = ((const unsigned char*)wl)[(size_t)l * C + c] != 0;
        else    t = ((const unsigned*)wl)[(size_t)l * C + c] != 0u;
        if (t) {
            int p = atomicAdd(&g_union_n, 1);
            if (p < MAXU) { g_ucols[p] = c; g_ulab[p] = l; }
        }
    }
}

// ---- K_main: one block per sample row; no SMEM row staging (pass2 hits L2) ----
__global__ __launch_bounds__(TPB) void k_main(const float* __restrict__ x,
                                              const float* __restrict__ y,
                                              int C, int L) {
    __shared__ __align__(8) float cand[CAP];
    __shared__ float tmaxs[TPB];
    __shared__ int   hist[256];
    __shared__ float sfirst[8];
    __shared__ unsigned s_gt, s_umax, s_lab[8], s_prefix;
    __shared__ int   s_candn, s_kk;
    __shared__ float s_m, s_x16;

    const int tid = threadIdx.x;
    const int b   = blockIdx.x;
    const float* xr = x + (size_t)b * C;
    const float* yr = y + (size_t)b * C;

    if (tid == 0) { s_gt = 0u; s_candn = 0; s_umax = 0u; s_prefix = 0u; s_kk = 16; }
    if (tid < 8)  s_lab[tid] = 0u;   // ordkey 0 is below every real float
    __syncthreads();

    int un = g_union_n; if (un > MAXU) un = MAXU;

    // --- gather y at union columns -> gt-label bits ---
    for (int i = tid; i < un; i += TPB) {
        int c = g_ucols[i];
        if (__ldg(yr + c) > 0.0f) atomicOr(&s_gt, 1u << g_ulab[i]);
    }

    // --- pass 1: stream x (LDG.128, peel to 16B), per-thread running max ---
    float tmax = -INFINITY;
    int peel, nv;
    {
        int off = (int)(((uintptr_t)xr & 15u) >> 2);
        peel = (4 - off) & 3; if (peel > C) peel = C;
        for (int c = tid; c < peel; c += TPB)
            tmax = fmaxf(tmax, __ldg(xr + c));
        nv = (C - peel) >> 2;
        const float4* xv = (const float4*)(xr + peel);
        #pragma unroll 4
        for (int i = tid; i < nv; i += TPB) {
            float4 v = __ldg(xv + i);
            tmax = fmaxf(tmax, fmaxf(fmaxf(v.x, v.y), fmaxf(v.z, v.w)));
        }
        for (int c = peel + (nv << 2) + tid; c < C; c += TPB)
            tmax = fmaxf(tmax, __ldg(xr + c));
    }
    tmaxs[tid] = tmax;

    // x[b, 0..7] snapshot (non_gt quirk uses xs[:, :L]) — L1/L2 hit
    if (tid < 8) sfirst[tid] = (tid < C) ? __ldg(xr + tid) : -INFINITY;
    __syncthreads();

    // --- union max + per-label max (scattered, L2-resident after pass 1) ---
    for (int i = tid; i < un; i += TPB) {
        unsigned k = ordf(__ldg(xr + g_ucols[i]));
        atomicMax(&s_umax, k);
        atomicMax(&s_lab[g_ulab[i]], k);
    }

    // --- m = 16th largest of 256 thread maxima (lower bound on global 16th) ---
    if (tid < 32) {
        float mval = -INFINITY;
        for (int r = 0; r < 16; ++r) {
            unsigned long long lb = 0ull;
            #pragma unroll
            for (int j = 0; j < 8; ++j) {
                int s = tid + 32 * j;
                unsigned long long k =
                    ((unsigned long long)ordf(tmaxs[s]) << 32) | (unsigned)s;
                if (k > lb) lb = k;
            }
            #pragma unroll
            for (int off = 16; off; off >>= 1) {
                unsigned long long o = __shfl_xor_sync(0xffffffffu, lb, off);
                if (o > lb) lb = o;
            }
            if (tid == 0) tmaxs[(int)(lb & 0xffffffffull)] = -INFINITY;
            mval = unordf((unsigned)(lb >> 32));
            __syncwarp();
        }
        if (tid == 0) s_m = mval;
    }
    __syncthreads();

    // --- pass 2 (L2 hit, float4): gather ALL values >= m (count >= 16) ---
    float m = s_m;
    {
        for (int c = tid; c < peel; c += TPB) {
            float v = __ldg(xr + c);
            if (v >= m) { int p = atomicAdd(&s_candn, 1); if (p < CAP) cand[p] = v; }
        }
        const float4* xv = (const float4*)(xr + peel);
        for (int i = tid; i < nv; i += TPB) {
            float4 v = __ldg(xv + i);
            float mx = fmaxf(fmaxf(v.x, v.y), fmaxf(v.z, v.w));
            if (mx >= m) {
                if (v.x >= m) { int p = atomicAdd(&s_candn, 1); if (p < CAP) cand[p] = v.x; }
                if (v.y >= m) { int p = atomicAdd(&s_candn, 1); if (p < CAP) cand[p] = v.y; }
                if (v.z >= m) { int p = atomicAdd(&s_candn, 1); if (p < CAP) cand[p] = v.z; }
                if (v.w >= m) { int p = atomicAdd(&s_candn, 1); if (p < CAP) cand[p] = v.w; }
            }
        }
        for (int c = peel + (nv << 2) + tid; c < C; c += TPB) {
            float v = __ldg(xr + c);
            if (v >= m) { int p = atomicAdd(&s_candn, 1); if (p < CAP) cand[p] = v; }
        }
    }
    __syncthreads();

    int nc = s_candn;
    if (nc <= CAP) {
        // fast path: 16 warp argmax-with-removal rounds over candidates
        if (tid < 32) {
            float xv16 = -INFINITY;
            for (int r = 0; r < 16; ++r) {
                unsigned long long lb = 0ull;
                for (int i = tid; i < nc; i += 32) {
                    unsigned long long k =
                        ((unsigned long long)ordf(cand[i]) << 32) | (unsigned)i;
                    if (k > lb) lb = k;
                }
                #pragma unroll
                for (int off = 16; off; off >>= 1) {
                    unsigned long long o = __shfl_xor_sync(0xffffffffu, lb, off);
                    if (o > lb) lb = o;
                }
                if (tid == 0) cand[(int)(lb & 0xffffffffull)] = -INFINITY;
                xv16 = unordf((unsigned)(lb >> 32));
                __syncwarp();
            }
            if (tid == 0) s_x16 = xv16;
        }
    } else {
        // rare fallback: mutation-free radix select (MSB->LSB) over L2 row
        for (int pos = 3; pos >= 0; --pos) {
            for (int i = tid; i < 256; i += TPB) hist[i] = 0;
            __syncthreads();
            unsigned pfx = s_prefix;
            unsigned hi_mask = 0u;
            if (pos < 3) hi_mask = 0xFFFFFFFFu << ((pos + 1) * 8);
            for (int c = tid; c < C; c += TPB) {
                unsigned key = ordf(__ldg(xr + c));
                if (((key ^ pfx) & hi_mask) == 0u)
                    atomicAdd(&hist[(key >> (pos * 8)) & 0xFF], 1);
            }
            __syncthreads();
            if (tid == 0) {
                int cum = 0, kk = s_kk;
                for (int v = 255; v >= 0; --v) {
                    int h = hist[v];
                    if (cum + h >= kk) {
                        s_prefix = pfx | ((unsigned)v << (pos * 8));
                        s_kk = kk - cum;
                        break;
                    }
                    cum += h;
                }
            }
            __syncthreads();
        }
        if (tid == 0) s_x16 = unordf(s_prefix);
    }
    __syncthreads();

    // --- final scalar math for this row ---
    if (tid == 0) {
        unsigned gt = s_gt;
        float x16   = s_x16;
        float thres = sigf(fmaxf(x16, 0.0f));   // == max(sig(x16), 0.5)
        float x1, x2;
        if (gt) {
            int fg = __ffs(gt) - 1;             // first gt label
            x1 = sigf(unordf(s_lab[fg]));
            float ngr = -INFINITY;
            bool anyng = false;
            int Lc = (L < 8) ? L : 8;
            for (int l = 0; l < Lc; ++l) {
                if (!((gt >> l) & 1u)) { ngr = fmaxf(ngr, sfirst[l]); anyng = true; }
            }
            float nongt = anyng ? sigf(ngr) : 0.0f;  // ref quirk: xs[:, :L], init 0
            x2 = fmaxf(nongt, thres);
        } else {
            x1 = thres;
            x2 = sigf(unordf(s_umax));
        }
        float d = x2 - x1 + 0.1f;
        float s = 1.0f / (1.0f + expf(-10.0f * d));
        g_rank[b] = (d > 0.0f) ? 5.0f * s : s;
    }
}

// ---- K_reduce: deterministic fixed-order reduction of per-row ranks ----
__global__ void k_reduce(float* __restrict__ out, int B) {
    __shared__ float ss[256];
    float s = 0.0f;
    for (int i = threadIdx.x; i < B; i += 256) s += g_rank[i];
    ss[threadIdx.x] = s;
    __syncthreads();
    for (int h = 128; h; h >>= 1) {
        if (threadIdx.x < h) ss[threadIdx.x] += ss[threadIdx.x + h];
        __syncthreads();
    }
    if (threadIdx.x == 0) out[0] = ss[0];
}

extern "C" void kernel_launch(void* const* d_in, const int* in_sizes, int n_in,
                              void* d_out, int out_size) {
    const float* x  = (const float*)d_in[0];
    const float* y  = (const float*)d_in[1];
    // d_in[2] = y_neg: dead code in the reference, never read.
    const void*  wl = d_in[3];

    const int L  = 8;
    const int LC = in_sizes[3];      // L * C elements
    const int C  = LC / L;           // 9605
    const int B  = in_sizes[0] / C;  // 4096

    k_reset<<<1, 1>>>();
    const int nwords = LC / 4;       // safe under both 1B and 4B layouts
    k_detect<<<(nwords + 255) / 256, 256>>>((const unsigned*)wl, nwords);
    k_build<<<(C + 255) / 256, 256>>>(wl, C, L);
    k_main<<<B, TPB>>>(x, y, C, L);
    k_reduce<<<1, 256>>>((float*)d_out, B);
}

// round 12
// speedup vs baseline: 1.8180x; 1.3147x over previous
#include <cuda_runtime.h>
#include <cstdint>

#define TPB 256
#define NKEEP 768          // 3 kept values per thread
#define MAXU 1024

// ---- device-global scratch (no allocations allowed) ----
__device__ int   g_union_n;   // zeroed by k_reduce tail (and static init)
__device__ int   g_weird;
__device__ int   g_ucols[MAXU];
__device__ int   g_ulab[MAXU];
__device__ float g_rank[8192];

// ---- monotone float <-> orderable uint mapping ----
__device__ __forceinline__ unsigned ordf(float f) {
    unsigned u = __float_as_uint(f);
    return (u & 0x80000000u) ? ~u : (u | 0x80000000u);
}
__device__ __forceinline__ float unordf(unsigned k) {
    unsigned u = (k & 0x80000000u) ? (k & 0x7fffffffu) : ~k;
    return __uint_as_float(u);
}
__device__ __forceinline__ float sigf(float v) { return 1.0f / (1.0f + expf(-v)); }

// ---- K_detect: wl dtype sniff. Words of int32{0,1}/float32{0,1.0f} are in
// {0,1,0x3F800000}; a 1-byte bool layout puts a true byte at offset%4!=0. ----
__global__ void k_detect(const unsigned* __restrict__ w, int n) {
    int i = blockIdx.x * blockDim.x + threadIdx.x;
    if (i < n) {
        unsigned v = w[i];
        if (v != 0u && v != 1u && v != 0x3F800000u) atomicOr(&g_weird, 1);
    }
}

// ---- K_build: compact (col,label) union list; label sets are disjoint. ----
__global__ void k_build(const void* __restrict__ wl, int C, int L) {
    int c = blockIdx.x * blockDim.x + threadIdx.x;
    if (c >= C) return;
    const int e1 = g_weird;  // 1 => 1-byte elements
    for (int l = 0; l < L; ++l) {
        bool t;
        if (e1) t = ((const unsigned char*)wl)[(size_t)l * C + c] != 0;
        else    t = ((const unsigned*)wl)[(size_t)l * C + c] != 0u;
        if (t) {
            int p = atomicAdd(&g_union_n, 1);
            if (p < MAXU) { g_ucols[p] = c; g_ulab[p] = l; }
        }
    }
}

// ---- block radix select: 16th-largest key; keys from cand[] or ordf(row) ----
__device__ __forceinline__ void radix16(const float* __restrict__ xr,
                                        const unsigned* __restrict__ cand,
                                        bool use_row, int nelem,
                                        int* hist, unsigned* s_prefix, int* s_kk,
                                        int tid) {
    if (tid == 0) { *s_prefix = 0u; *s_kk = 16; }
    for (int pos = 3; pos >= 0; --pos) {
        hist[tid] = 0;
        __syncthreads();               // orders prefix/kk writes + hist zero
        const unsigned pfx = *s_prefix;
        const unsigned hi_mask = (pos < 3) ? (0xFFFFFFFFu << ((pos + 1) * 8)) : 0u;
        for (int i = tid; i < nelem; i += TPB) {
            unsigned key = use_row ? ordf(__ldg(xr + i)) : cand[i];
            if (((key ^ pfx) & hi_mask) == 0u)
                atomicAdd(&hist[(key >> (pos * 8)) & 0xFFu], 1);
        }
        __syncthreads();
        if (tid < 32) {
            int kk = *s_kk;
            int base = 255 - tid * 8;          // descending 8-bin group
            int part = 0;
            #pragma unroll
            for (int j = 0; j < 8; ++j) part += hist[base - j];
            int cum = part;
            #pragma unroll
            for (int off = 1; off < 32; off <<= 1) {
                int o = __shfl_up_sync(0xffffffffu, cum, off);
                if (tid >= off) cum += o;
            }
            unsigned ball = __ballot_sync(0xffffffffu, cum >= kk);
            int t = __ffs(ball) - 1;
            if (tid == t) {
                int above = cum - part;
                int v = 255 - t * 8;
                for (;; --v) { int h = hist[v]; if (above + h >= kk) break; above += h; }
                *s_prefix = pfx | ((unsigned)v << (pos * 8));
                *s_kk = kk - above;
            }
        }
        __syncthreads();
    }
}

// ---- K_main: one block per row; single DRAM pass with per-thread top-3 ----
__global__ __launch_bounds__(TPB) void k_main(const float* __restrict__ x,
                                              const float* __restrict__ y,
                                              int C, int L) {
    __shared__ unsigned cand[NKEEP];
    __shared__ int      hist[256];
    __shared__ float    sfirst[8];
    __shared__ unsigned s_gt, s_umax, s_lab[8], s_prefix;
    __shared__ int      s_kk, s_flag;

    const int tid = threadIdx.x;
    const int b   = blockIdx.x;
    const float* xr = x + (size_t)b * C;
    const float* yr = y + (size_t)b * C;

    if (tid == 0) { s_gt = 0u; s_umax = 0u; s_flag = 0; }
    if (tid < 8)  s_lab[tid] = 0u;   // ordkey 0 is below every real float key
    __syncthreads();

    int un = g_union_n; if (un > MAXU) un = MAXU;

    // ===== phase A: gathers + single full stream with per-thread top-3 =====
    for (int i = tid; i < un; i += TPB) {
        int c = g_ucols[i], l = g_ulab[i];
        if (__ldg(yr + c) > 0.0f) atomicOr(&s_gt, 1u << l);
        unsigned k = ordf(__ldg(xr + c));
        atomicMax(&s_umax, k);
        atomicMax(&s_lab[l], k);
    }
    if (tid < 8) sfirst[tid] = (tid < C) ? __ldg(xr + tid) : -INFINITY;

    float t0 = -INFINITY, t1 = -INFINITY, t2 = -INFINITY;  // t0 >= t1 >= t2
    {
        int off = (int)(((uintptr_t)xr & 15u) >> 2);
        int peel = (4 - off) & 3; if (peel > C) peel = C;
        for (int c = tid; c < peel; c += TPB) {
            float v = __ldg(xr + c);
            if (v > t2) { if (v > t1) { t2 = t1; if (v > t0) { t1 = t0; t0 = v; } else t1 = v; } else t2 = v; }
        }
        const int nv4 = (C - peel) >> 2;
        const float4* xv = (const float4*)(xr + peel);
        #pragma unroll 4
        for (int i = tid; i < nv4; i += TPB) {
            float4 q = __ldg(xv + i);
            float v;
            v = q.x; if (v > t2) { if (v > t1) { t2 = t1; if (v > t0) { t1 = t0; t0 = v; } else t1 = v; } else t2 = v; }
            v = q.y; if (v > t2) { if (v > t1) { t2 = t1; if (v > t0) { t1 = t0; t0 = v; } else t1 = v; } else t2 = v; }
            v = q.z; if (v > t2) { if (v > t1) { t2 = t1; if (v > t0) { t1 = t0; t0 = v; } else t1 = v; } else t2 = v; }
            v = q.w; if (v > t2) { if (v > t1) { t2 = t1; if (v > t0) { t1 = t0; t0 = v; } else t1 = v; } else t2 = v; }
        }
        for (int c = peel + (nv4 << 2) + tid; c < C; c += TPB) {
            float v = __ldg(xr + c);
            if (v > t2) { if (v > t1) { t2 = t1; if (v > t0) { t1 = t0; t0 = v; } else t1 = v; } else t2 = v; }
        }
    }
    const unsigned k2 = ordf(t2);
    cand[tid]       = ordf(t0);
    cand[256 + tid] = ordf(t1);
    cand[512 + tid] = k2;
    __syncthreads();

    // ===== phase B: t = 16th largest of the 768 kept keys =====
    radix16(xr, cand, /*use_row=*/false, NKEEP, hist, &s_prefix, &s_kk, tid);

    // ===== exactness check: some thread's 3rd-largest strictly above t ?
    // If not: every non-kept element <= its thread's t2 <= t, so all elements
    // > t are kept and t == x_sorted[15] exactly (equality-safe by counting).
    if (k2 > s_prefix) atomicOr(&s_flag, 1);
    __syncthreads();
    if (s_flag) {   // rare (~1% of rows): exact select over the full row (L2)
        radix16(xr, cand, /*use_row=*/true, C, hist, &s_prefix, &s_kk, tid);
    }

    // ===== phase E: final scalar math =====
    if (tid == 0) {
        unsigned gt = s_gt;
        float x16   = unordf(s_prefix);
        float thres = sigf(fmaxf(x16, 0.0f));   // == max(sig(x16), 0.5)
        float x1, x2;
        if (gt) {
            int fg = __ffs(gt) - 1;             // first gt label
            x1 = sigf(unordf(s_lab[fg]));
            float ngr = -INFINITY;
            bool anyng = false;
            int Lc = (L < 8) ? L : 8;
            for (int l = 0; l < Lc; ++l) {
                if (!((gt >> l) & 1u)) { ngr = fmaxf(ngr, sfirst[l]); anyng = true; }
            }
            float nongt = anyng ? sigf(ngr) : 0.0f;  // ref quirk: xs[:, :L], init 0
            x2 = fmaxf(nongt, thres);
        } else {
            x1 = thres;
            x2 = sigf(unordf(s_umax));
        }
        float d = x2 - x1 + 0.1f;
        float s = 1.0f / (1.0f + expf(-10.0f * d));
        g_rank[b] = (d > 0.0f) ? 5.0f * s : s;
    }
}

// ---- K_reduce: fixed-order sum + reset globals for the next launch ----
__global__ void k_reduce(float* __restrict__ out, int B) {
    __shared__ float ss[256];
    float s = 0.0f;
    for (int i = threadIdx.x; i < B; i += 256) s += g_rank[i];
    ss[threadIdx.x] = s;
    __syncthreads();
    for (int h = 128; h; h >>= 1) {
        if (threadIdx.x < h) ss[threadIdx.x] += ss[threadIdx.x + h];
        __syncthreads();
    }
    if (threadIdx.x == 0) {
        out[0] = ss[0];
        g_union_n = 0;    // leave state zeroed for the next launch
        g_weird   = 0;
    }
}

extern "C" void kernel_launch(void* const* d_in, const int* in_sizes, int n_in,
                              void* d_out, int out_size) {
    const float* x  = (const float*)d_in[0];
    const float* y  = (const float*)d_in[1];
    // d_in[2] = y_neg: dead code in the reference, never read.
    const void*  wl = d_in[3];

    const int L  = 8;
    const int LC = in_sizes[3];      // L * C elements
    const int C  = LC / L;           // 9605
    const int B  = in_sizes[0] / C;  // 4096

    const int nwords = LC / 4;       // safe under both 1B and 4B layouts
    k_detect<<<(nwords + 255) / 256, 256>>>((const unsigned*)wl, nwords);
    k_build<<<(C + 255) / 256, 256>>>(wl, C, L);
    k_main<<<B, TPB>>>(x, y, C, L);
    k_reduce<<<1, 256>>>((float*)d_out, B);
}

// round 17
// speedup vs baseline: 1.8323x; 1.0079x over previous
#include <cuda_runtime.h>
#include <cstdint>

#define TPB 256
#define NKEEP 768          // 3 kept values per thread
#define MAXU 1024

// ---- device-global scratch (no allocations allowed) ----
__device__ int   g_union_n;   // zeroed by k_reduce tail (and static init)
__device__ int   g_weird;
__device__ int   g_ucols[MAXU];
__device__ int   g_ulab[MAXU];
__device__ float g_rank[8192];

// ---- monotone float <-> orderable uint mapping ----
__device__ __forceinline__ unsigned ordf(float f) {
    unsigned u = __float_as_uint(f);
    return (u & 0x80000000u) ? ~u : (u | 0x80000000u);
}
__device__ __forceinline__ float unordf(unsigned k) {
    unsigned u = (k & 0x80000000u) ? (k & 0x7fffffffu) : ~k;
    return __uint_as_float(u);
}
__device__ __forceinline__ float sigf(float v) { return 1.0f / (1.0f + expf(-v)); }

// ---- K_detect: wl dtype sniff. Words of int32{0,1}/float32{0,1.0f} are in
// {0,1,0x3F800000}; a 1-byte bool layout puts a true byte at offset%4!=0. ----
__global__ void k_detect(const unsigned* __restrict__ w, int n) {
    int i = blockIdx.x * blockDim.x + threadIdx.x;
    if (i < n) {
        unsigned v = w[i];
        if (v != 0u && v != 1u && v != 0x3F800000u) atomicOr(&g_weird, 1);
    }
}

// ---- K_build: compact (col,label) union list; label sets are disjoint. ----
__global__ void k_build(const void* __restrict__ wl, int C, int L) {
    int c = blockIdx.x * blockDim.x + threadIdx.x;
    if (c >= C) return;
    const int e1 = g_weird;  // 1 => 1-byte elements
    for (int l = 0; l < L; ++l) {
        bool t;
        if (e1) t = ((const unsigned char*)wl)[(size_t)l * C + c] != 0;
        else    t = ((const unsigned*)wl)[(size_t)l * C + c] != 0u;
        if (t) {
            int p = atomicAdd(&g_union_n, 1);
            if (p < MAXU) { g_ucols[p] = c; g_ulab[p] = l; }
        }
    }
}

// ---- block radix select: 16th-largest key; keys from cand[] or ordf(row) ----
__device__ __forceinline__ void radix16(const float* __restrict__ xr,
                                        const unsigned* __restrict__ cand,
                                        bool use_row, int nelem,
                                        int* hist, unsigned* s_prefix, int* s_kk,
                                        int tid) {
    if (tid == 0) { *s_prefix = 0u; *s_kk = 16; }
    for (int pos = 3; pos >= 0; --pos) {
        hist[tid] = 0;
        __syncthreads();               // orders prefix/kk writes + hist zero
        const unsigned pfx = *s_prefix;
        const unsigned hi_mask = (pos < 3) ? (0xFFFFFFFFu << ((pos + 1) * 8)) : 0u;
        for (int i = tid; i < nelem; i += TPB) {
            unsigned key = use_row ? ordf(__ldg(xr + i)) : cand[i];
            if (((key ^ pfx) & hi_mask) == 0u)
                atomicAdd(&hist[(key >> (pos * 8)) & 0xFFu], 1);
        }
        __syncthreads();
        if (tid < 32) {
            int kk = *s_kk;
            int base = 255 - tid * 8;          // descending 8-bin group
            int part = 0;
            #pragma unroll
            for (int j = 0; j < 8; ++j) part += hist[base - j];
            int cum = part;
            #pragma unroll
            for (int off = 1; off < 32; off <<= 1) {
                int o = __shfl_up_sync(0xffffffffu, cum, off);
                if (tid >= off) cum += o;
            }
            unsigned ball = __ballot_sync(0xffffffffu, cum >= kk);
            int t = __ffs(ball) - 1;
            if (tid == t) {
                int above = cum - part;
                int v = 255 - t * 8;
                for (;; --v) { int h = hist[v]; if (above + h >= kk) break; above += h; }
                *s_prefix = pfx | ((unsigned)v << (pos * 8));
                *s_kk = kk - above;
            }
        }
        __syncthreads();
    }
}

// ---- K_main: one block per row; single DRAM pass with per-thread top-3 ----
__global__ __launch_bounds__(TPB) void k_main(const float* __restrict__ x,
                                              const float* __restrict__ y,
                                              int C, int L) {
    __shared__ unsigned cand[NKEEP];
    __shared__ int      hist[256];
    __shared__ float    sfirst[8];
    __shared__ unsigned s_gt, s_umax, s_lab[8], s_prefix;
    __shared__ int      s_kk, s_flag;

    const int tid = threadIdx.x;
    const int b   = blockIdx.x;
    const float* xr = x + (size_t)b * C;
    const float* yr = y + (size_t)b * C;

    if (tid == 0) { s_gt = 0u; s_umax = 0u; s_flag = 0; }
    if (tid < 8)  s_lab[tid] = 0u;   // ordkey 0 is below every real float key
    __syncthreads();

    int un = g_union_n; if (un > MAXU) un = MAXU;

    // ===== phase A: gathers + single full stream with per-thread top-3 =====
    for (int i = tid; i < un; i += TPB) {
        int c = g_ucols[i], l = g_ulab[i];
        if (__ldg(yr + c) > 0.0f) atomicOr(&s_gt, 1u << l);
        unsigned k = ordf(__ldg(xr + c));
        atomicMax(&s_umax, k);
        atomicMax(&s_lab[l], k);
    }
    if (tid < 8) sfirst[tid] = (tid < C) ? __ldg(xr + tid) : -INFINITY;

    float t0 = -INFINITY, t1 = -INFINITY, t2 = -INFINITY;  // t0 >= t1 >= t2
    {
        int off = (int)(((uintptr_t)xr & 15u) >> 2);
        int peel = (4 - off) & 3; if (peel > C) peel = C;
        for (int c = tid; c < peel; c += TPB) {
            float v = __ldg(xr + c);
            if (v > t2) { if (v > t1) { t2 = t1; if (v > t0) { t1 = t0; t0 = v; } else t1 = v; } else t2 = v; }
        }
        const int nv4 = (C - peel) >> 2;
        const float4* xv = (const float4*)(xr + peel);
        #pragma unroll 8
        for (int i = tid; i < nv4; i += TPB) {
            float4 q = __ldg(xv + i);
            float v;
            v = q.x; if (v > t2) { if (v > t1) { t2 = t1; if (v > t0) { t1 = t0; t0 = v; } else t1 = v; } else t2 = v; }
            v = q.y; if (v > t2) { if (v > t1) { t2 = t1; if (v > t0) { t1 = t0; t0 = v; } else t1 = v; } else t2 = v; }
            v = q.z; if (v > t2) { if (v > t1) { t2 = t1; if (v > t0) { t1 = t0; t0 = v; } else t1 = v; } else t2 = v; }
            v = q.w; if (v > t2) { if (v > t1) { t2 = t1; if (v > t0) { t1 = t0; t0 = v; } else t1 = v; } else t2 = v; }
        }
        for (int c = peel + (nv4 << 2) + tid; c < C; c += TPB) {
            float v = __ldg(xr + c);
            if (v > t2) { if (v > t1) { t2 = t1; if (v > t0) { t1 = t0; t0 = v; } else t1 = v; } else t2 = v; }
        }
    }
    const unsigned k2 = ordf(t2);
    cand[tid]       = ordf(t0);
    cand[256 + tid] = ordf(t1);
    cand[512 + tid] = k2;
    __syncthreads();

    // ===== phase B: t = 16th largest of the 768 kept keys =====
    radix16(xr, cand, /*use_row=*/false, NKEEP, hist, &s_prefix, &s_kk, tid);

    // ===== exactness check: some thread's 3rd-largest strictly above t ?
    // If not: every non-kept element <= its thread's t2 <= t, so all elements
    // > t are kept and t == x_sorted[15] exactly (equality-safe by counting).
    if (k2 > s_prefix) atomicOr(&s_flag, 1);
    __syncthreads();
    if (s_flag) {   // rare: exact select over the full row (L2-resident)
        radix16(xr, cand, /*use_row=*/true, C, hist, &s_prefix, &s_kk, tid);
    }

    // ===== phase E: final scalar math =====
    if (tid == 0) {
        unsigned gt = s_gt;
        float x16   = unordf(s_prefix);
        float thres = sigf(fmaxf(x16, 0.0f));   // == max(sig(x16), 0.5)
        float x1, x2;
        if (gt) {
            int fg = __ffs(gt) - 1;             // first gt label
            x1 = sigf(unordf(s_lab[fg]));
            float ngr = -INFINITY;
            bool anyng = false;
            int Lc = (L < 8) ? L : 8;
            for (int l = 0; l < Lc; ++l) {
                if (!((gt >> l) & 1u)) { ngr = fmaxf(ngr, sfirst[l]); anyng = true; }
            }
            float nongt = anyng ? sigf(ngr) : 0.0f;  // ref quirk: xs[:, :L], init 0
            x2 = fmaxf(nongt, thres);
        } else {
            x1 = thres;
            x2 = sigf(unordf(s_umax));
        }
        float d = x2 - x1 + 0.1f;
        float s = 1.0f / (1.0f + expf(-10.0f * d));
        g_rank[b] = (d > 0.0f) ? 5.0f * s : s;
    }
}

// ---- K_reduce: 1024-thread fixed-order sum + reset globals ----
__global__ void k_reduce(float* __restrict__ out, int B) {
    __shared__ float ss[32];
    const int tid = threadIdx.x;
    float s = 0.0f;
    for (int i = tid; i < B; i += 1024) s += g_rank[i];   // 4 iters at B=4096
    // fixed-order intra-warp tree (deterministic lane pairing)
    #pragma unroll
    for (int off = 16; off; off >>= 1)
        s += __shfl_xor_sync(0xffffffffu, s, off);
    if ((tid & 31) == 0) ss[tid >> 5] = s;
    __syncthreads();
    if (tid < 32) {
        float v = ss[tid];
        #pragma unroll
        for (int off = 16; off; off >>= 1)
            v += __shfl_xor_sync(0xffffffffu, v, off);
        if (tid == 0) {
            out[0] = v;
            g_union_n = 0;    // leave state zeroed for the next launch
            g_weird   = 0;
        }
    }
}

extern "C" void kernel_launch(void* const* d_in, const int* in_sizes, int n_in,
                              void* d_out, int out_size) {
    const float* x  = (const float*)d_in[0];
    const float* y  = (const float*)d_in[1];
    // d_in[2] = y_neg: dead code in the reference, never read.
    const void*  wl = d_in[3];

    const int L  = 8;
    const int LC = in_sizes[3];      // L * C elements
    const int C  = LC / L;           // 9605
    const int B  = in_sizes[0] / C;  // 4096

    const int nwords = LC / 4;       // safe under both 1B and 4B layouts
    k_detect<<<(nwords + 255) / 256, 256>>>((const unsigned*)wl, nwords);
    k_build<<<(C + 255) / 256, 256>>>(wl, C, L);
    k_main<<<B, TPB>>>(x, y, C, L);
    k_reduce<<<1, 1024>>>((float*)d_out, B);
}